// round 8
// baseline (speedup 1.0000x reference)
#include <cuda_runtime.h>
#include <math.h>
#include <cstdint>

// ---------------- problem constants ----------------
#define BATCH 512
#define NH 4
#define KD 16
#define DD 64
#define DIM 256
#define QO 96
#define RESX 14
#define NPIX 196

typedef unsigned long long ull;

// global scratch
__device__ __align__(128) float g_cat_t[(size_t)BATCH * NPIX * DIM];
__device__ __align__(128) float g_wt[DIM * DIM];
__device__ __align__(128) float g_abmat[NH * NPIX * NPIX + 16];

__device__ __forceinline__ float to_tf32(float x) {
    float r; asm("cvt.rna.satfinite.tf32.f32 %0, %1;" : "=f"(r) : "f"(x)); return r;
}
__device__ __forceinline__ uint32_t smem_u32(const void* p) {
    uint32_t a;
    asm("{ .reg .u64 t; cvta.to.shared.u64 t, %1; cvt.u32.u64 %0, t; }" : "=r"(a) : "l"(p));
    return a;
}
// fragment-pack permutation: block of 8 cols -> pairs (j, j+4) adjacent
__device__ __forceinline__ int pidx(int m) {
    return (m & ~7) + ((m & 3) * 2) + ((m >> 2) & 1);
}

// ---------------- cp.async helpers ----------------
#define CP_ASYNC16(dst_u32, src_ptr) \
    asm volatile("cp.async.cg.shared.global [%0], [%1], 16;" :: "r"(dst_u32), "l"(src_ptr))
#define CP_COMMIT() asm volatile("cp.async.commit_group;" ::: "memory")
#define CP_WAIT0()  asm volatile("cp.async.wait_group 0;" ::: "memory")

// ---------------- mma.sync tf32 m16n8k8 ----------------
__device__ __forceinline__ void mma_tf32(float* d, const uint32_t* a, const uint32_t* b) {
    asm volatile(
        "mma.sync.aligned.m16n8k8.row.col.f32.tf32.tf32.f32 "
        "{%0,%1,%2,%3}, {%4,%5,%6,%7}, {%8,%9}, {%0,%1,%2,%3};"
        : "+f"(d[0]), "+f"(d[1]), "+f"(d[2]), "+f"(d[3])
        : "r"(a[0]), "r"(a[1]), "r"(a[2]), "r"(a[3]), "r"(b[0]), "r"(b[1]));
}
__device__ __forceinline__ void mma8(float* d, float a0, float a1, float a2, float a3,
                                     float b0, float b1) {
    uint32_t A[4] = {__float_as_uint(a0), __float_as_uint(a1),
                     __float_as_uint(a2), __float_as_uint(a3)};
    uint32_t B[2] = {__float_as_uint(b0), __float_as_uint(b1)};
    mma_tf32(d, A, B);
}

// ---------------- cascade smem layout (float offsets) ----------------
#define CF_FEAT 0            // 200 x 68
#define CF_QT   13600        // 224 x 18
#define CF_KT   17632        // 224 x 18
#define CF_QG   21664        // 224 x 18
#define CF_V    25696        // 64 x 200  packed
#define CF_S    38496        // 2 x (32 x 200)  packed double buffer (aliases wq)
#define CF_WQ   CF_S         // 96 x 68
#define CF_QSC  51296
#define CF_QBI  51392
#define CF_DSC  51488
#define CF_DBI  51504
#define CF_DWW  51520
#define CF_END  51920
#define SMEM1_BYTES (CF_END * 4)      // 207680

__global__ void __launch_bounds__(1024, 1)
cascade_kernel(const float* __restrict__ x,
               const float* __restrict__ qkv_w,
               const float* __restrict__ qkv_scale,
               const float* __restrict__ qkv_bias,
               const float* __restrict__ dw_w,
               const float* __restrict__ dw_scale,
               const float* __restrict__ dw_bias)
{
    extern __shared__ float sm[];
    float* featT = sm + CF_FEAT;
    float* qT    = sm + CF_QT;
    float* kT    = sm + CF_KT;
    float* qgT   = sm + CF_QG;
    float* vv    = sm + CF_V;
    float* wq    = sm + CF_WQ;
    float* qsc   = sm + CF_QSC;
    float* qbi   = sm + CF_QBI;
    float* dsc   = sm + CF_DSC;
    float* dbi   = sm + CF_DBI;
    float* dww   = sm + CF_DWW;

    const int b    = blockIdx.x;
    const int tid  = threadIdx.x;
    const int warp = tid >> 5;    // 0..31
    const int lane = tid & 31;
    const int g    = lane >> 2;   // 0..7
    const int tig  = lane & 3;    // 0..3

    // one-time zero padding
    for (int idx = tid; idx < 28 * 18; idx += 1024) qgT[196 * 18 + idx] = 0.f;
    if (tid < 4 * 68) featT[196 * 68 + tid] = 0.f;
    if (tid >= 512 && tid < 768) {                 // vv pad slots
        int t = tid - 512;
        int d = t >> 2, s = t & 3;
        vv[d * 200 + 193 + 2 * s] = 0.f;
    }
    __syncthreads();

    for (int i = 0; i < NH; i++) {
        // ---------- Phase A ----------
        {
            const float* xb = x + ((size_t)b * DIM + i * DD) * NPIX;
            if (i == 0) {
                for (int idx = tid; idx < DD * NPIX; idx += 1024) {
                    int c = idx / NPIX, n = idx - c * NPIX;
                    featT[n * 68 + c] = to_tf32(xb[idx]);
                }
            } else {
                for (int idx = tid; idx < DD * NPIX; idx += 1024) {
                    int c = idx / NPIX, n = idx - c * NPIX;
                    featT[n * 68 + c] = to_tf32(featT[n * 68 + c] + xb[idx]);
                }
            }
            for (int idx = tid; idx < QO * 64; idx += 1024)
                wq[(idx >> 6) * 68 + (idx & 63)] = to_tf32(qkv_w[i * QO * 64 + idx]);
            if (tid < 400) dww[tid] = dw_w[i * 400 + tid];
            if (tid >= 416 && tid < 416 + QO) {
                int o = tid - 416;
                qsc[o] = qkv_scale[i * QO + o]; qbi[o] = qkv_bias[i * QO + o];
            }
            if (tid >= 544 && tid < 544 + KD) {
                int c = tid - 544;
                dsc[c] = dw_scale[i * KD + c]; dbi[c] = dw_bias[i * KD + c];
            }
        }
        __syncthreads();

        // ---------- Phase B: QKV via mma, 75 (nt,mp) tasks over 32 warps ----------
        for (int t = warp; t < 75; t += 32) {
            const int nt = t / 3, mp = t - nt * 3;
            const int nb0 = nt * 8;
            float B0[8], B1[8];
            #pragma unroll
            for (int ks = 0; ks < 8; ks++) {
                B0[ks] = featT[(nb0 + g) * 68 + ks * 8 + tig];
                B1[ks] = featT[(nb0 + g) * 68 + ks * 8 + tig + 4];
            }
            const int oX = (2 * mp) * 16, oY = (2 * mp + 1) * 16;
            float dd0[4] = {0.f, 0.f, 0.f, 0.f};
            float dd1[4] = {0.f, 0.f, 0.f, 0.f};
            #pragma unroll
            for (int ks = 0; ks < 8; ks++) {
                mma8(dd0, wq[(oX + g) * 68 + ks * 8 + tig],
                          wq[(oX + g + 8) * 68 + ks * 8 + tig],
                          wq[(oX + g) * 68 + ks * 8 + tig + 4],
                          wq[(oX + g + 8) * 68 + ks * 8 + tig + 4],
                          B0[ks], B1[ks]);
                mma8(dd1, wq[(oY + g) * 68 + ks * 8 + tig],
                          wq[(oY + g + 8) * 68 + ks * 8 + tig],
                          wq[(oY + g) * 68 + ks * 8 + tig + 4],
                          wq[(oY + g + 8) * 68 + ks * 8 + tig + 4],
                          B0[ks], B1[ks]);
            }
            #pragma unroll
            for (int h = 0; h < 2; h++) {
                const int mt = 2 * mp + h;
                float* dd = h ? dd1 : dd0;
                const int oA = mt * 16 + g, oB = oA + 8;
                const float sA = qsc[oA], bA = qbi[oA];
                const float sB = qsc[oB], bB = qbi[oB];
                float y0 = dd[0] * sA + bA, y1 = dd[1] * sA + bA;
                float y2 = dd[2] * sB + bB, y3 = dd[3] * sB + bB;
                const int nc = nb0 + 2 * tig;
                if (mt == 0) {
                    qT[nc * 18 + oA] = y0; qT[(nc + 1) * 18 + oA] = y1;
                    qT[nc * 18 + oB] = y2; qT[(nc + 1) * 18 + oB] = y3;
                } else if (mt == 1) {
                    int c0 = oA - 16, c1 = oB - 16;
                    kT[nc * 18 + c0] = to_tf32(y0); kT[(nc + 1) * 18 + c0] = to_tf32(y1);
                    kT[nc * 18 + c1] = to_tf32(y2); kT[(nc + 1) * 18 + c1] = to_tf32(y3);
                } else {
                    int dA = oA - 32, dB = oB - 32;
                    if (nc < 196) {
                        vv[dA * 200 + pidx(nc)] = to_tf32(y0);
                        vv[dB * 200 + pidx(nc)] = to_tf32(y2);
                    }
                    if (nc + 1 < 196) {
                        vv[dA * 200 + pidx(nc + 1)] = to_tf32(y1);
                        vv[dB * 200 + pidx(nc + 1)] = to_tf32(y3);
                    }
                }
            }
        }
        __syncthreads();

        // ---------- Phase C ----------
        for (int t = tid; t < KD * NPIX; t += 1024) {
            int n = t >> 4, c = t & 15;
            int py = n / RESX, px = n - py * RESX;
            float s = 0.f;
            #pragma unroll
            for (int dy = 0; dy < 5; dy++) {
                int yy = py + dy - 2;
                if (yy < 0 || yy >= RESX) continue;
                #pragma unroll
                for (int dx = 0; dx < 5; dx++) {
                    int xx = px + dx - 2;
                    if (xx < 0 || xx >= RESX) continue;
                    s += dww[c * 25 + dy * 5 + dx] * qT[(yy * RESX + xx) * 18 + c];
                }
            }
            float dq = s * dsc[c] + dbi[c];
            float gl = 0.5f * dq * (1.0f + erff(dq * 0.70710678118654752440f));
            qgT[n * 18 + c] = to_tf32(gl + qT[n * 18 + c]);
        }
        __syncthreads();

        const float* abm = g_abmat + (size_t)i * (NPIX * NPIX);
        float* gcb = g_cat_t + ((size_t)b * NPIX) * DIM + i * DD;

        // ---------- Phase D: pipelined 32-row tiles (7 tiles, last = 4 rows) ----------
        // QK for tile t into S[t&1]. Steady state: warps 16-31 compute QK(t+1)
        // while warps 0-15 do softmax(t)+AV(t).
        #define QK_TILE(T, SDST, WBASE, WNUM)                                            \
        do {                                                                             \
            const int r0q = (T) * 32;                                                    \
            const int mts = ((T) < 6) ? 2 : 1;                                           \
            for (int tk = warp - (WBASE); tk < mts * 25; tk += (WNUM)) {                 \
                const int mt = tk / 25, nt = tk - mt * 25;                               \
                const int mm0 = nt * 8;                                                  \
                float b00 = kT[(mm0 + g) * 18 + tig],     b01 = kT[(mm0 + g) * 18 + tig + 4];  \
                float b10 = kT[(mm0 + g) * 18 + tig + 8], b11 = kT[(mm0 + g) * 18 + tig + 12]; \
                const int rr = r0q + mt * 16;                                            \
                float dd[4] = {0.f, 0.f, 0.f, 0.f};                                      \
                mma8(dd, qgT[(rr + g) * 18 + tig],     qgT[(rr + g + 8) * 18 + tig],     \
                         qgT[(rr + g) * 18 + tig + 4], qgT[(rr + g + 8) * 18 + tig + 4], \
                         b00, b01);                                                      \
                mma8(dd, qgT[(rr + g) * 18 + tig + 8],  qgT[(rr + g + 8) * 18 + tig + 8],   \
                         qgT[(rr + g) * 18 + tig + 12], qgT[(rr + g + 8) * 18 + tig + 12],  \
                         b10, b11);                                                      \
                const int nlA = mt * 16 + g, nlB = nlA + 8;                              \
                const int ngA = min(r0q + nlA, 195), ngB = min(r0q + nlB, 195);          \
                const int m0 = mm0 + 2 * tig;                                            \
                float2 abA = *(const float2*)&abm[(size_t)ngA * NPIX + m0];              \
                float2 abB = *(const float2*)&abm[(size_t)ngB * NPIX + m0];              \
                (SDST)[nlA * 200 + pidx(m0)]     = dd[0] * 0.25f + abA.x;                \
                (SDST)[nlA * 200 + pidx(m0 + 1)] = dd[1] * 0.25f + abA.y;                \
                (SDST)[nlB * 200 + pidx(m0)]     = dd[2] * 0.25f + abB.x;                \
                (SDST)[nlB * 200 + pidx(m0 + 1)] = dd[3] * 0.25f + abB.y;                \
            }                                                                            \
        } while (0)

        float* S0 = sm + CF_S;
        float* S1 = sm + CF_S + 32 * 200;

        QK_TILE(0, S0, 0, 32);
        __syncthreads();

        for (int t = 0; t < 7; t++) {
            float* Scur = (t & 1) ? S1 : S0;
            if (warp < 16) {
                // softmax on this tile's rows
                const int rows = (t < 6) ? 32 : 4;
                for (int r = warp; r < rows; r += 16) {
                    float e[7];
                    float mx = -1e30f;
                    #pragma unroll
                    for (int j = 0; j < 7; j++) {
                        int m = lane + 32 * j;
                        float vva = (m < NPIX) ? Scur[r * 200 + pidx(m)] : -1e30f;
                        e[j] = vva;
                        mx = fmaxf(mx, vva);
                    }
                    #pragma unroll
                    for (int off = 16; off; off >>= 1)
                        mx = fmaxf(mx, __shfl_xor_sync(0xffffffffu, mx, off));
                    float sum = 0.f;
                    #pragma unroll
                    for (int j = 0; j < 7; j++) { e[j] = __expf(e[j] - mx); sum += e[j]; }
                    #pragma unroll
                    for (int off = 16; off; off >>= 1)
                        sum += __shfl_xor_sync(0xffffffffu, sum, off);
                    float inv = 1.0f / sum;
                    #pragma unroll
                    for (int j = 0; j < 7; j++) {
                        int m = lane + 32 * j;
                        if (m < NPIX) Scur[r * 200 + pidx(m)] = to_tf32(e[j] * inv);
                    }
                    if (lane < 4) Scur[r * 200 + 193 + 2 * lane] = 0.f;
                }
                asm volatile("bar.sync 1, 512;" ::: "memory");
                // AV: 2 quarters x 8 d-blocks = 16 single-chain warps
                const int r0 = t * 32;
                const int qa = warp >> 3;        // 0..1
                const int db = warp & 7;
                if (t < 6 || qa == 0) {
                    const int d0c = db * 8;
                    const int rl = qa * 16 + g, rh = rl + 8;
                    float dd[4] = {0.f, 0.f, 0.f, 0.f};
                    #pragma unroll
                    for (int ks = 0; ks < 25; ks++) {
                        const int ko = ks * 8 + tig * 2;
                        float2 bv = *(const float2*)&vv[(d0c + g) * 200 + ko];
                        float2 l0 = *(const float2*)&Scur[rl * 200 + ko];
                        float2 h0 = *(const float2*)&Scur[rh * 200 + ko];
                        mma8(dd, l0.x, h0.x, l0.y, h0.y, bv.x, bv.y);
                    }
                    const int dc = d0c + 2 * tig;
                    const int nA = r0 + rl, nB = r0 + rh;
                    if (nA < NPIX) {
                        *(float2*)&featT[nA * 68 + dc] = make_float2(dd[0], dd[1]);
                        *(float2*)&gcb[(size_t)nA * DIM + dc] =
                            make_float2(to_tf32(fmaxf(dd[0], 0.f)), to_tf32(fmaxf(dd[1], 0.f)));
                    }
                    if (nB < NPIX) {
                        *(float2*)&featT[nB * 68 + dc] = make_float2(dd[2], dd[3]);
                        *(float2*)&gcb[(size_t)nB * DIM + dc] =
                            make_float2(to_tf32(fmaxf(dd[2], 0.f)), to_tf32(fmaxf(dd[3], 0.f)));
                    }
                }
            } else {
                if (t + 1 < 7) {
                    float* Snxt = ((t + 1) & 1) ? S1 : S0;
                    QK_TILE(t + 1, Snxt, 16, 16);
                }
            }
            __syncthreads();
        }
        #undef QK_TILE
    }
}

// ---------------- prep kernels ----------------
__global__ void wprep_kernel(const float* __restrict__ proj_w) {
    int idx = blockIdx.x * 256 + threadIdx.x;
    g_wt[idx] = to_tf32(proj_w[idx]);
}
__global__ void abprep_kernel(const float* __restrict__ attention_biases,
                              const int* __restrict__ bias_idxs) {
    int idx = blockIdx.x * 256 + threadIdx.x;
    if (idx < NH * NPIX * NPIX) {
        int h = idx / (NPIX * NPIX);
        int nm = idx - h * (NPIX * NPIX);
        g_abmat[idx] = attention_biases[h * NPIX + bias_idxs[nm]];
    }
}

// ---------------- proj kernel: mma.sync tf32 GEMM ----------------
#define PJ_NT 128
#define PJ_AS 36
#define PJ_A_FLOATS (256 * PJ_AS)
#define PJ_B_FLOATS (128 * PJ_AS)
#define PJ_BUF_FLOATS (PJ_A_FLOATS + PJ_B_FLOATS)
#define PJ_SMEM_BYTES (2 * PJ_BUF_FLOATS * 4)

__global__ void __launch_bounds__(256, 1)
proj_mma_kernel(const float* __restrict__ proj_scale,
                const float* __restrict__ proj_bias,
                float* __restrict__ out)
{
    extern __shared__ float smf[];
    const uint32_t smem_base = smem_u32(smf);

    const int tid  = threadIdx.x;
    const int wid  = tid >> 5;
    const int lane = tid & 31;
    const int g    = lane >> 2;
    const int tig  = lane & 3;
    const int n0   = blockIdx.x * PJ_NT;

    const int o0 = (wid & 3) * 64;
    const int nb = (wid >> 2) * 64;

    float acc[4][8][4];
    #pragma unroll
    for (int mi = 0; mi < 4; mi++)
        #pragma unroll
        for (int ni = 0; ni < 8; ni++)
            #pragma unroll
            for (int c = 0; c < 4; c++) acc[mi][ni][c] = 0.f;

    auto issue_chunk = [&](int c) {
        const int buf = c & 1;
        const int k0 = c * 32;
        const uint32_t abase = smem_base + (uint32_t)(buf * PJ_BUF_FLOATS) * 4u;
        const uint32_t bbase = abase + (uint32_t)PJ_A_FLOATS * 4u;
        #pragma unroll
        for (int it = 0; it < 8; it++) {
            int idx = it * 256 + tid;
            int row = idx >> 3, k4 = idx & 7;
            CP_ASYNC16(abase + (uint32_t)(row * PJ_AS + k4 * 4) * 4u,
                       g_wt + (size_t)row * 256 + k0 + k4 * 4);
        }
        #pragma unroll
        for (int it = 0; it < 4; it++) {
            int idx = it * 256 + tid;
            int row = idx >> 3, k4 = idx & 7;
            CP_ASYNC16(bbase + (uint32_t)(row * PJ_AS + k4 * 4) * 4u,
                       g_cat_t + (size_t)(n0 + row) * 256 + k0 + k4 * 4);
        }
        CP_COMMIT();
    };

    issue_chunk(0);

    for (int c = 0; c < 8; c++) {
        CP_WAIT0();
        __syncthreads();
        if (c < 7) issue_chunk(c + 1);

        const int buf = c & 1;
        const uint32_t* Asu = (const uint32_t*)(smf + buf * PJ_BUF_FLOATS);
        const uint32_t* Bsu = Asu + PJ_A_FLOATS;
        const int a_base = (o0 + g) * PJ_AS + tig;
        const int b_base = (nb + g) * PJ_AS + tig;

        #pragma unroll
        for (int k8 = 0; k8 < 32; k8 += 8) {
            uint32_t a[4][4];
            #pragma unroll
            for (int mi = 0; mi < 4; mi++) {
                int ab = a_base + mi * (16 * PJ_AS) + k8;
                a[mi][0] = Asu[ab];
                a[mi][1] = Asu[ab + 8 * PJ_AS];
                a[mi][2] = Asu[ab + 4];
                a[mi][3] = Asu[ab + 8 * PJ_AS + 4];
            }
            uint32_t bfr[8][2];
            #pragma unroll
            for (int ni = 0; ni < 8; ni++) {
                int bb = b_base + ni * (8 * PJ_AS) + k8;
                bfr[ni][0] = Bsu[bb];
                bfr[ni][1] = Bsu[bb + 4];
            }
            #pragma unroll
            for (int mi = 0; mi < 4; mi++)
                #pragma unroll
                for (int ni = 0; ni < 8; ni++)
                    mma_tf32(acc[mi][ni], a[mi], bfr[ni]);
        }
        __syncthreads();
    }

    float* Ssm = smf;
    #pragma unroll
    for (int h = 0; h < 2; h++) {
        __syncthreads();
        if ((wid >> 2) == h) {
            #pragma unroll
            for (int mi = 0; mi < 4; mi++) {
                int orow = o0 + mi * 16 + g;
                #pragma unroll
                for (int ni = 0; ni < 8; ni++) {
                    int nl = ni * 8 + 2 * tig;
                    *(float2*)&Ssm[orow * 68 + nl] =
                        make_float2(acc[mi][ni][0], acc[mi][ni][1]);
                    *(float2*)&Ssm[(orow + 8) * 68 + nl] =
                        make_float2(acc[mi][ni][2], acc[mi][ni][3]);
                }
            }
        }
        __syncthreads();
        #pragma unroll 4
        for (int it = 0; it < 64; it++) {
            int idx = it * 256 + tid;
            int o = idx >> 6, nn = idx & 63;
            float v = Ssm[o * 68 + nn];
            v = v * proj_scale[o] + proj_bias[o];
            unsigned ng = (unsigned)(n0 + h * 64 + nn);
            unsigned bb = ng / 196u;
            unsigned pp = ng - bb * 196u;
            out[(size_t)bb * (DIM * NPIX) + (size_t)o * NPIX + pp] = v;
        }
    }
}

extern "C" void kernel_launch(void* const* d_in, const int* in_sizes, int n_in,
                              void* d_out, int out_size)
{
    (void)in_sizes; (void)n_in; (void)out_size;
    const float* x          = (const float*)d_in[0];
    const float* qkv_w      = (const float*)d_in[1];
    const float* qkv_scale  = (const float*)d_in[2];
    const float* qkv_bias   = (const float*)d_in[3];
    const float* dw_w       = (const float*)d_in[4];
    const float* dw_scale   = (const float*)d_in[5];
    const float* dw_bias    = (const float*)d_in[6];
    const float* proj_w     = (const float*)d_in[7];
    const float* proj_scale = (const float*)d_in[8];
    const float* proj_bias  = (const float*)d_in[9];
    const float* attn_b     = (const float*)d_in[10];
    const int*   bias_idxs  = (const int*)d_in[11];
    float* out = (float*)d_out;

    cudaFuncSetAttribute(cascade_kernel, cudaFuncAttributeMaxDynamicSharedMemorySize, SMEM1_BYTES);
    cudaFuncSetAttribute(proj_mma_kernel, cudaFuncAttributeMaxDynamicSharedMemorySize, PJ_SMEM_BYTES);

    // order: abprep -> cascade -> wprep -> proj (valid deps; puts cascade at ncu -s 5 slot)
    abprep_kernel<<<(NH * NPIX * NPIX + 255) / 256, 256>>>(attn_b, bias_idxs);
    cascade_kernel<<<BATCH, 1024, SMEM1_BYTES>>>(x, qkv_w, qkv_scale, qkv_bias,
                                                 dw_w, dw_scale, dw_bias);
    wprep_kernel<<<DIM * DIM / 256, 256>>>(proj_w);
    proj_mma_kernel<<<(BATCH * NPIX) / PJ_NT, 256, PJ_SMEM_BYTES>>>(proj_scale, proj_bias, out);
}

// round 9
// speedup vs baseline: 1.2169x; 1.2169x over previous
#include <cuda_runtime.h>
#include <math.h>
#include <cstdint>

// ---------------- problem constants ----------------
#define BATCH 512
#define NH 4
#define KD 16
#define DD 64
#define DIM 256
#define QO 96
#define RESX 14
#define NPIX 196

typedef unsigned long long ull;

// global scratch
__device__ __align__(128) float g_cat_t[(size_t)BATCH * NPIX * DIM];
__device__ __align__(128) float g_wt[DIM * DIM];
__device__ __align__(128) float g_abmat[NH * NPIX * NPIX + 16];

__device__ __forceinline__ float to_tf32(float x) {
    float r; asm("cvt.rna.satfinite.tf32.f32 %0, %1;" : "=f"(r) : "f"(x)); return r;
}
__device__ __forceinline__ uint32_t smem_u32(const void* p) {
    uint32_t a;
    asm("{ .reg .u64 t; cvta.to.shared.u64 t, %1; cvt.u32.u64 %0, t; }" : "=r"(a) : "l"(p));
    return a;
}
// fragment-pack permutation: block of 8 cols -> pairs (j, j+4) adjacent
__device__ __forceinline__ int pidx(int m) {
    return (m & ~7) + ((m & 3) * 2) + ((m >> 2) & 1);
}

// ---------------- cp.async helpers ----------------
#define CP_ASYNC16(dst_u32, src_ptr) \
    asm volatile("cp.async.cg.shared.global [%0], [%1], 16;" :: "r"(dst_u32), "l"(src_ptr))
#define CP_COMMIT() asm volatile("cp.async.commit_group;" ::: "memory")
#define CP_WAIT0()  asm volatile("cp.async.wait_group 0;" ::: "memory")

// ---------------- mma.sync tf32 m16n8k8 ----------------
__device__ __forceinline__ void mma_tf32(float* d, const uint32_t* a, const uint32_t* b) {
    asm volatile(
        "mma.sync.aligned.m16n8k8.row.col.f32.tf32.tf32.f32 "
        "{%0,%1,%2,%3}, {%4,%5,%6,%7}, {%8,%9}, {%0,%1,%2,%3};"
        : "+f"(d[0]), "+f"(d[1]), "+f"(d[2]), "+f"(d[3])
        : "r"(a[0]), "r"(a[1]), "r"(a[2]), "r"(a[3]), "r"(b[0]), "r"(b[1]));
}
__device__ __forceinline__ void mma8(float* d, float a0, float a1, float a2, float a3,
                                     float b0, float b1) {
    uint32_t A[4] = {__float_as_uint(a0), __float_as_uint(a1),
                     __float_as_uint(a2), __float_as_uint(a3)};
    uint32_t B[2] = {__float_as_uint(b0), __float_as_uint(b1)};
    mma_tf32(d, A, B);
}

// ---------------- cascade smem layout (float offsets) ----------------
#define CF_FEAT 0            // 200 x 68
#define CF_QT   13600        // 224 x 18
#define CF_KT   17632        // 224 x 18
#define CF_QG   21664        // 224 x 18
#define CF_V    25696        // 64 x 200 packed
#define CF_WQ   38496        // 96 x 68
#define CF_QSC  45024
#define CF_QBI  45120
#define CF_DSC  45216
#define CF_DBI  45232
#define CF_DWW  45248
#define CF_END  45648
#define SMEM1_BYTES (CF_END * 4)      // 182592

__global__ void __launch_bounds__(512, 1)
cascade_kernel(const float* __restrict__ x,
               const float* __restrict__ qkv_w,
               const float* __restrict__ qkv_scale,
               const float* __restrict__ qkv_bias,
               const float* __restrict__ dw_w,
               const float* __restrict__ dw_scale,
               const float* __restrict__ dw_bias)
{
    extern __shared__ float sm[];
    float* featT = sm + CF_FEAT;
    float* qT    = sm + CF_QT;
    float* kT    = sm + CF_KT;
    float* qgT   = sm + CF_QG;
    float* vv    = sm + CF_V;
    float* wq    = sm + CF_WQ;
    float* qsc   = sm + CF_QSC;
    float* qbi   = sm + CF_QBI;
    float* dsc   = sm + CF_DSC;
    float* dbi   = sm + CF_DBI;
    float* dww   = sm + CF_DWW;

    const int b    = blockIdx.x;
    const int tid  = threadIdx.x;
    const int warp = tid >> 5;    // 0..15
    const int lane = tid & 31;
    const int g    = lane >> 2;   // 0..7
    const int tig  = lane & 3;    // 0..3

    // one-time zero padding (qgT + kT pad rows; featT pad rows; vv pad slots)
    for (int idx = tid; idx < 28 * 18; idx += 512) {
        qgT[196 * 18 + idx] = 0.f;
        kT[196 * 18 + idx] = 0.f;
    }
    if (tid < 4 * 68) featT[196 * 68 + tid] = 0.f;
    if (tid < 256) {
        int d = tid >> 2, s = tid & 3;
        vv[d * 200 + 193 + 2 * s] = 0.f;
    }
    __syncthreads();

    for (int i = 0; i < NH; i++) {
        // ---------- Phase A: feat accumulate + staging ----------
        {
            const float* xb = x + ((size_t)b * DIM + i * DD) * NPIX;
            if (i == 0) {
                for (int idx = tid; idx < DD * NPIX; idx += 512) {
                    int c = idx / NPIX, n = idx - c * NPIX;
                    featT[n * 68 + c] = to_tf32(xb[idx]);
                }
            } else {
                for (int idx = tid; idx < DD * NPIX; idx += 512) {
                    int c = idx / NPIX, n = idx - c * NPIX;
                    featT[n * 68 + c] = to_tf32(featT[n * 68 + c] + xb[idx]);
                }
            }
            for (int idx = tid; idx < QO * 64; idx += 512)
                wq[(idx >> 6) * 68 + (idx & 63)] = to_tf32(qkv_w[i * QO * 64 + idx]);
            if (tid < 400) dww[tid] = dw_w[i * 400 + tid];
            if (tid >= 400 && tid < 416) {
                int c = tid - 400;
                dsc[c] = dw_scale[i * KD + c]; dbi[c] = dw_bias[i * KD + c];
            }
            if (tid >= 416) {
                int o = tid - 416;
                qsc[o] = qkv_scale[i * QO + o]; qbi[o] = qkv_bias[i * QO + o];
            }
        }
        __syncthreads();

        // ---------- Phase B: QKV via mma, 75 (nt,mp) tasks over 16 warps ----------
        for (int t = warp; t < 75; t += 16) {
            const int nt = t / 3, mp = t - nt * 3;
            const int nb0 = nt * 8;
            float B0[8], B1[8];
            #pragma unroll
            for (int ks = 0; ks < 8; ks++) {
                B0[ks] = featT[(nb0 + g) * 68 + ks * 8 + tig];
                B1[ks] = featT[(nb0 + g) * 68 + ks * 8 + tig + 4];
            }
            const int oX = (2 * mp) * 16, oY = (2 * mp + 1) * 16;
            float dd0[4] = {0.f, 0.f, 0.f, 0.f};
            float dd1[4] = {0.f, 0.f, 0.f, 0.f};
            #pragma unroll
            for (int ks = 0; ks < 8; ks++) {
                mma8(dd0, wq[(oX + g) * 68 + ks * 8 + tig],
                          wq[(oX + g + 8) * 68 + ks * 8 + tig],
                          wq[(oX + g) * 68 + ks * 8 + tig + 4],
                          wq[(oX + g + 8) * 68 + ks * 8 + tig + 4],
                          B0[ks], B1[ks]);
                mma8(dd1, wq[(oY + g) * 68 + ks * 8 + tig],
                          wq[(oY + g + 8) * 68 + ks * 8 + tig],
                          wq[(oY + g) * 68 + ks * 8 + tig + 4],
                          wq[(oY + g + 8) * 68 + ks * 8 + tig + 4],
                          B0[ks], B1[ks]);
            }
            #pragma unroll
            for (int h = 0; h < 2; h++) {
                const int mt = 2 * mp + h;
                float* dd = h ? dd1 : dd0;
                const int oA = mt * 16 + g, oB = oA + 8;
                const float sA = qsc[oA], bA = qbi[oA];
                const float sB = qsc[oB], bB = qbi[oB];
                float y0 = dd[0] * sA + bA, y1 = dd[1] * sA + bA;
                float y2 = dd[2] * sB + bB, y3 = dd[3] * sB + bB;
                const int nc = nb0 + 2 * tig;
                if (mt == 0) {
                    qT[nc * 18 + oA] = y0; qT[(nc + 1) * 18 + oA] = y1;
                    qT[nc * 18 + oB] = y2; qT[(nc + 1) * 18 + oB] = y3;
                } else if (mt == 1) {
                    int c0 = oA - 16, c1 = oB - 16;
                    kT[nc * 18 + c0] = to_tf32(y0); kT[(nc + 1) * 18 + c0] = to_tf32(y1);
                    kT[nc * 18 + c1] = to_tf32(y2); kT[(nc + 1) * 18 + c1] = to_tf32(y3);
                } else {
                    int dA = oA - 32, dB = oB - 32;
                    if (nc < 196) {
                        vv[dA * 200 + pidx(nc)] = to_tf32(y0);
                        vv[dB * 200 + pidx(nc)] = to_tf32(y2);
                    }
                    if (nc + 1 < 196) {
                        vv[dA * 200 + pidx(nc + 1)] = to_tf32(y1);
                        vv[dB * 200 + pidx(nc + 1)] = to_tf32(y3);
                    }
                }
            }
        }
        __syncthreads();

        // ---------- Phase C: depthwise 5x5 conv + affine + GELU + residual ----------
        for (int t = tid; t < KD * NPIX; t += 512) {
            int n = t >> 4, c = t & 15;
            int py = n / RESX, px = n - py * RESX;
            float s = 0.f;
            #pragma unroll
            for (int dy = 0; dy < 5; dy++) {
                int yy = py + dy - 2;
                if (yy < 0 || yy >= RESX) continue;
                #pragma unroll
                for (int dx = 0; dx < 5; dx++) {
                    int xx = px + dx - 2;
                    if (xx < 0 || xx >= RESX) continue;
                    s += dww[c * 25 + dy * 5 + dx] * qT[(yy * RESX + xx) * 18 + c];
                }
            }
            float dq = s * dsc[c] + dbi[c];
            float gl = 0.5f * dq * (1.0f + erff(dq * 0.70710678118654752440f));
            qgT[n * 18 + c] = to_tf32(gl + qT[n * 18 + c]);
        }
        __syncthreads();

        // ---------- Phase D: warp-owned 16-row stripes, barrier-free ----------
        const float* abm = g_abmat + (size_t)i * (NPIX * NPIX);
        float* gcb = g_cat_t + ((size_t)b * NPIX) * DIM + i * DD;

        if (warp < 13) {
            const int r0 = warp * 16;
            // qg A-frags (persist for both passes)
            float aq0 = qgT[(r0 + g) * 18 + tig],      aq1 = qgT[(r0 + g + 8) * 18 + tig];
            float aq2 = qgT[(r0 + g) * 18 + tig + 4],  aq3 = qgT[(r0 + g + 8) * 18 + tig + 4];
            float aq4 = qgT[(r0 + g) * 18 + tig + 8],  aq5 = qgT[(r0 + g + 8) * 18 + tig + 8];
            float aq6 = qgT[(r0 + g) * 18 + tig + 12], aq7 = qgT[(r0 + g + 8) * 18 + tig + 12];
            const int ngA = min(r0 + g, 195), ngB = min(r0 + g + 8, 195);
            const float* abrA = abm + (size_t)ngA * NPIX;
            const float* abrB = abm + (size_t)ngB * NPIX;
            const int m0l = 2 * tig;

            // pass 1: row max
            float Mg = -1e30f, Mg8 = -1e30f;
            #pragma unroll 5
            for (int nt = 0; nt < 25; nt++) {
                const int mm0 = nt * 8;
                float b00 = kT[(mm0 + g) * 18 + tig],     b01 = kT[(mm0 + g) * 18 + tig + 4];
                float b10 = kT[(mm0 + g) * 18 + tig + 8], b11 = kT[(mm0 + g) * 18 + tig + 12];
                float dd[4] = {0.f, 0.f, 0.f, 0.f};
                mma8(dd, aq0, aq1, aq2, aq3, b00, b01);
                mma8(dd, aq4, aq5, aq6, aq7, b10, b11);
                const int m0 = mm0 + m0l;
                float2 abA = *(const float2*)&abrA[m0];
                float2 abB = *(const float2*)&abrB[m0];
                float s00 = dd[0] * 0.25f + abA.x;
                float s01 = dd[1] * 0.25f + abA.y;
                float s10 = dd[2] * 0.25f + abB.x;
                float s11 = dd[3] * 0.25f + abB.y;
                if (m0 >= NPIX)     { s00 = -1e30f; s10 = -1e30f; }
                if (m0 + 1 >= NPIX) { s01 = -1e30f; s11 = -1e30f; }
                Mg  = fmaxf(Mg,  fmaxf(s00, s01));
                Mg8 = fmaxf(Mg8, fmaxf(s10, s11));
            }
            Mg  = fmaxf(Mg,  __shfl_xor_sync(0xffffffffu, Mg, 1));
            Mg  = fmaxf(Mg,  __shfl_xor_sync(0xffffffffu, Mg, 2));
            Mg8 = fmaxf(Mg8, __shfl_xor_sync(0xffffffffu, Mg8, 1));
            Mg8 = fmaxf(Mg8, __shfl_xor_sync(0xffffffffu, Mg8, 2));

            // pass 2: exp + AV (P stays in registers, re-laid via shuffles)
            float o[8][4];
            #pragma unroll
            for (int j = 0; j < 8; j++) { o[j][0] = o[j][1] = o[j][2] = o[j][3] = 0.f; }
            float lg = 0.f, lg8 = 0.f;
            const int srcA = (g << 2) | (tig >> 1);
            const int srcB = srcA + 2;
            const bool odd = (tig & 1);

            #pragma unroll 5
            for (int nt = 0; nt < 25; nt++) {
                const int mm0 = nt * 8;
                float b00 = kT[(mm0 + g) * 18 + tig],     b01 = kT[(mm0 + g) * 18 + tig + 4];
                float b10 = kT[(mm0 + g) * 18 + tig + 8], b11 = kT[(mm0 + g) * 18 + tig + 12];
                float dd[4] = {0.f, 0.f, 0.f, 0.f};
                mma8(dd, aq0, aq1, aq2, aq3, b00, b01);
                mma8(dd, aq4, aq5, aq6, aq7, b10, b11);
                const int m0 = mm0 + m0l;
                float2 abA = *(const float2*)&abrA[m0];
                float2 abB = *(const float2*)&abrB[m0];
                float s00 = dd[0] * 0.25f + abA.x;
                float s01 = dd[1] * 0.25f + abA.y;
                float s10 = dd[2] * 0.25f + abB.x;
                float s11 = dd[3] * 0.25f + abB.y;
                if (m0 >= NPIX)     { s00 = -1e30f; s10 = -1e30f; }
                if (m0 + 1 >= NPIX) { s01 = -1e30f; s11 = -1e30f; }
                float p00 = to_tf32(__expf(s00 - Mg));
                float p01 = to_tf32(__expf(s01 - Mg));
                float p10 = to_tf32(__expf(s10 - Mg8));
                float p11 = to_tf32(__expf(s11 - Mg8));
                lg  += p00 + p01;
                lg8 += p10 + p11;
                // re-lay D-frag cols (2tig,2tig+1) -> A-frag cols (tig, tig+4)
                float t0 = __shfl_sync(0xffffffffu, p00, srcA);
                float t1 = __shfl_sync(0xffffffffu, p01, srcA);
                float a0 = odd ? t1 : t0;
                float u0 = __shfl_sync(0xffffffffu, p10, srcA);
                float u1 = __shfl_sync(0xffffffffu, p11, srcA);
                float a1 = odd ? u1 : u0;
                float t2 = __shfl_sync(0xffffffffu, p00, srcB);
                float t3 = __shfl_sync(0xffffffffu, p01, srcB);
                float a2 = odd ? t3 : t2;
                float u2 = __shfl_sync(0xffffffffu, p10, srcB);
                float u3 = __shfl_sync(0xffffffffu, p11, srcB);
                float a3 = odd ? u3 : u2;
                #pragma unroll
                for (int j = 0; j < 8; j++) {
                    float2 bv = *(const float2*)&vv[(j * 8 + g) * 200 + mm0 + m0l];
                    mma8(o[j], a0, a1, a2, a3, bv.x, bv.y);
                }
            }
            lg  += __shfl_xor_sync(0xffffffffu, lg, 1);
            lg  += __shfl_xor_sync(0xffffffffu, lg, 2);
            lg8 += __shfl_xor_sync(0xffffffffu, lg8, 1);
            lg8 += __shfl_xor_sync(0xffffffffu, lg8, 2);
            float ivg = 1.0f / lg, ivg8 = 1.0f / lg8;

            const int nA = r0 + g, nB = r0 + g + 8;
            #pragma unroll
            for (int j = 0; j < 8; j++) {
                const int dc = j * 8 + 2 * tig;
                if (nA < NPIX) {
                    float v0 = o[j][0] * ivg, v1 = o[j][1] * ivg;
                    *(float2*)&featT[nA * 68 + dc] = make_float2(v0, v1);
                    *(float2*)&gcb[(size_t)nA * DIM + dc] =
                        make_float2(to_tf32(fmaxf(v0, 0.f)), to_tf32(fmaxf(v1, 0.f)));
                }
                if (nB < NPIX) {
                    float v2 = o[j][2] * ivg8, v3 = o[j][3] * ivg8;
                    *(float2*)&featT[nB * 68 + dc] = make_float2(v2, v3);
                    *(float2*)&gcb[(size_t)nB * DIM + dc] =
                        make_float2(to_tf32(fmaxf(v2, 0.f)), to_tf32(fmaxf(v3, 0.f)));
                }
            }
        }
        __syncthreads();
    }
}

// ---------------- prep kernels ----------------
__global__ void wprep_kernel(const float* __restrict__ proj_w) {
    int idx = blockIdx.x * 256 + threadIdx.x;
    g_wt[idx] = to_tf32(proj_w[idx]);
}
__global__ void abprep_kernel(const float* __restrict__ attention_biases,
                              const int* __restrict__ bias_idxs) {
    int idx = blockIdx.x * 256 + threadIdx.x;
    if (idx < NH * NPIX * NPIX) {
        int h = idx / (NPIX * NPIX);
        int nm = idx - h * (NPIX * NPIX);
        g_abmat[idx] = attention_biases[h * NPIX + bias_idxs[nm]];
    }
}

// ---------------- proj kernel: mma.sync tf32 GEMM (unchanged) ----------------
#define PJ_NT 128
#define PJ_AS 36
#define PJ_A_FLOATS (256 * PJ_AS)
#define PJ_B_FLOATS (128 * PJ_AS)
#define PJ_BUF_FLOATS (PJ_A_FLOATS + PJ_B_FLOATS)
#define PJ_SMEM_BYTES (2 * PJ_BUF_FLOATS * 4)

__global__ void __launch_bounds__(256, 1)
proj_mma_kernel(const float* __restrict__ proj_scale,
                const float* __restrict__ proj_bias,
                float* __restrict__ out)
{
    extern __shared__ float smf[];
    const uint32_t smem_base = smem_u32(smf);

    const int tid  = threadIdx.x;
    const int wid  = tid >> 5;
    const int lane = tid & 31;
    const int g    = lane >> 2;
    const int tig  = lane & 3;
    const int n0   = blockIdx.x * PJ_NT;

    const int o0 = (wid & 3) * 64;
    const int nb = (wid >> 2) * 64;

    float acc[4][8][4];
    #pragma unroll
    for (int mi = 0; mi < 4; mi++)
        #pragma unroll
        for (int ni = 0; ni < 8; ni++)
            #pragma unroll
            for (int c = 0; c < 4; c++) acc[mi][ni][c] = 0.f;

    auto issue_chunk = [&](int c) {
        const int buf = c & 1;
        const int k0 = c * 32;
        const uint32_t abase = smem_base + (uint32_t)(buf * PJ_BUF_FLOATS) * 4u;
        const uint32_t bbase = abase + (uint32_t)PJ_A_FLOATS * 4u;
        #pragma unroll
        for (int it = 0; it < 8; it++) {
            int idx = it * 256 + tid;
            int row = idx >> 3, k4 = idx & 7;
            CP_ASYNC16(abase + (uint32_t)(row * PJ_AS + k4 * 4) * 4u,
                       g_wt + (size_t)row * 256 + k0 + k4 * 4);
        }
        #pragma unroll
        for (int it = 0; it < 4; it++) {
            int idx = it * 256 + tid;
            int row = idx >> 3, k4 = idx & 7;
            CP_ASYNC16(bbase + (uint32_t)(row * PJ_AS + k4 * 4) * 4u,
                       g_cat_t + (size_t)(n0 + row) * 256 + k0 + k4 * 4);
        }
        CP_COMMIT();
    };

    issue_chunk(0);

    for (int c = 0; c < 8; c++) {
        CP_WAIT0();
        __syncthreads();
        if (c < 7) issue_chunk(c + 1);

        const int buf = c & 1;
        const uint32_t* Asu = (const uint32_t*)(smf + buf * PJ_BUF_FLOATS);
        const uint32_t* Bsu = Asu + PJ_A_FLOATS;
        const int a_base = (o0 + g) * PJ_AS + tig;
        const int b_base = (nb + g) * PJ_AS + tig;

        #pragma unroll
        for (int k8 = 0; k8 < 32; k8 += 8) {
            uint32_t a[4][4];
            #pragma unroll
            for (int mi = 0; mi < 4; mi++) {
                int ab = a_base + mi * (16 * PJ_AS) + k8;
                a[mi][0] = Asu[ab];
                a[mi][1] = Asu[ab + 8 * PJ_AS];
                a[mi][2] = Asu[ab + 4];
                a[mi][3] = Asu[ab + 8 * PJ_AS + 4];
            }
            uint32_t bfr[8][2];
            #pragma unroll
            for (int ni = 0; ni < 8; ni++) {
                int bb = b_base + ni * (8 * PJ_AS) + k8;
                bfr[ni][0] = Bsu[bb];
                bfr[ni][1] = Bsu[bb + 4];
            }
            #pragma unroll
            for (int mi = 0; mi < 4; mi++)
                #pragma unroll
                for (int ni = 0; ni < 8; ni++)
                    mma_tf32(acc[mi][ni], a[mi], bfr[ni]);
        }
        __syncthreads();
    }

    float* Ssm = smf;
    #pragma unroll
    for (int h = 0; h < 2; h++) {
        __syncthreads();
        if ((wid >> 2) == h) {
            #pragma unroll
            for (int mi = 0; mi < 4; mi++) {
                int orow = o0 + mi * 16 + g;
                #pragma unroll
                for (int ni = 0; ni < 8; ni++) {
                    int nl = ni * 8 + 2 * tig;
                    *(float2*)&Ssm[orow * 68 + nl] =
                        make_float2(acc[mi][ni][0], acc[mi][ni][1]);
                    *(float2*)&Ssm[(orow + 8) * 68 + nl] =
                        make_float2(acc[mi][ni][2], acc[mi][ni][3]);
                }
            }
        }
        __syncthreads();
        #pragma unroll 4
        for (int it = 0; it < 64; it++) {
            int idx = it * 256 + tid;
            int o = idx >> 6, nn = idx & 63;
            float v = Ssm[o * 68 + nn];
            v = v * proj_scale[o] + proj_bias[o];
            unsigned ng = (unsigned)(n0 + h * 64 + nn);
            unsigned bb = ng / 196u;
            unsigned pp = ng - bb * 196u;
            out[(size_t)bb * (DIM * NPIX) + (size_t)o * NPIX + pp] = v;
        }
    }
}

extern "C" void kernel_launch(void* const* d_in, const int* in_sizes, int n_in,
                              void* d_out, int out_size)
{
    (void)in_sizes; (void)n_in; (void)out_size;
    const float* x          = (const float*)d_in[0];
    const float* qkv_w      = (const float*)d_in[1];
    const float* qkv_scale  = (const float*)d_in[2];
    const float* qkv_bias   = (const float*)d_in[3];
    const float* dw_w       = (const float*)d_in[4];
    const float* dw_scale   = (const float*)d_in[5];
    const float* dw_bias    = (const float*)d_in[6];
    const float* proj_w     = (const float*)d_in[7];
    const float* proj_scale = (const float*)d_in[8];
    const float* proj_bias  = (const float*)d_in[9];
    const float* attn_b     = (const float*)d_in[10];
    const int*   bias_idxs  = (const int*)d_in[11];
    float* out = (float*)d_out;

    cudaFuncSetAttribute(cascade_kernel, cudaFuncAttributeMaxDynamicSharedMemorySize, SMEM1_BYTES);
    cudaFuncSetAttribute(proj_mma_kernel, cudaFuncAttributeMaxDynamicSharedMemorySize, PJ_SMEM_BYTES);

    abprep_kernel<<<(NH * NPIX * NPIX + 255) / 256, 256>>>(attn_b, bias_idxs);
    cascade_kernel<<<BATCH, 512, SMEM1_BYTES>>>(x, qkv_w, qkv_scale, qkv_bias,
                                                dw_w, dw_scale, dw_bias);
    wprep_kernel<<<DIM * DIM / 256, 256>>>(proj_w);
    proj_mma_kernel<<<(BATCH * NPIX) / PJ_NT, 256, PJ_SMEM_BYTES>>>(proj_scale, proj_bias, out);
}